// round 1
// baseline (speedup 1.0000x reference)
#include <cuda_runtime.h>

#define B_SZ 8192
#define D_SZ 1024
#define E_SZ 32
#define A_SZ 128

// Per-batch gating weights produced by gating_kernel, consumed by main_kernel.
__device__ float g_weights[B_SZ * E_SZ];

// ---------------- f32x2 packed helpers ----------------
__device__ __forceinline__ unsigned long long pack2(float lo, float hi) {
    unsigned long long r;
    asm("mov.b64 %0, {%1, %2};" : "=l"(r) : "f"(lo), "f"(hi));
    return r;
}
__device__ __forceinline__ void unpack2(unsigned long long v, float &lo, float &hi) {
    asm("mov.b64 {%0, %1}, %2;" : "=f"(lo), "=f"(hi) : "l"(v));
}
__device__ __forceinline__ void ffma2(unsigned long long &d, unsigned long long a,
                                      unsigned long long b) {
    asm("fma.rn.f32x2 %0, %1, %2, %0;" : "+l"(d) : "l"(a), "l"(b));
}

// =====================================================================
// Kernel 1: gating. logits = x @ W_att^T + b_att + adaptive_bias,
// gumbel-softmax -> g_weights. Also seeds d_out with
// sum_e w[b,e]*b_strat[e,a] (bias term of the strategy linears).
// Grid: 128 blocks x 128 threads, each block owns 64 batch rows.
// =====================================================================
__global__ __launch_bounds__(128) void gating_kernel(
    const float* __restrict__ x, const float* __restrict__ W_att,
    const float* __restrict__ b_att, const float* __restrict__ abias,
    const float* __restrict__ b_strat, const float* __restrict__ gu,
    float* __restrict__ out)
{
    __shared__ float xs[32][64];    // [k][b]
    __shared__ float was[32][32];   // [k][e]
    __shared__ float L[64][33];     // logits, padded
    __shared__ float Wg[64][33];    // weights, padded

    const int tid = threadIdx.x;
    const int b0 = blockIdx.x * 64;
    const int tb = tid & 15;        // 16 groups of 4 b-rows
    const int te = tid >> 4;        // 8 groups of 4 experts

    float acc[4][4] = {};

    for (int d0 = 0; d0 < D_SZ; d0 += 32) {
        #pragma unroll
        for (int i = 0; i < 4; i++) {
            int f = tid + i * 128;
            int row = f >> 3, c4 = f & 7;
            float4 v = *(const float4*)&x[(size_t)(b0 + row) * D_SZ + d0 + c4 * 4];
            xs[c4 * 4 + 0][row] = v.x; xs[c4 * 4 + 1][row] = v.y;
            xs[c4 * 4 + 2][row] = v.z; xs[c4 * 4 + 3][row] = v.w;
        }
        #pragma unroll
        for (int i = 0; i < 2; i++) {
            int f = tid + i * 128;
            int row = f >> 3, c4 = f & 7;
            float4 v = *(const float4*)&W_att[(size_t)row * D_SZ + d0 + c4 * 4];
            was[c4 * 4 + 0][row] = v.x; was[c4 * 4 + 1][row] = v.y;
            was[c4 * 4 + 2][row] = v.z; was[c4 * 4 + 3][row] = v.w;
        }
        __syncthreads();
        #pragma unroll 8
        for (int kk = 0; kk < 32; kk++) {
            float4 av = *(const float4*)&xs[kk][tb * 4];
            float4 ev = *(const float4*)&was[kk][te * 4];
            float a_[4] = {av.x, av.y, av.z, av.w};
            float e_[4] = {ev.x, ev.y, ev.z, ev.w};
            #pragma unroll
            for (int i = 0; i < 4; i++)
                #pragma unroll
                for (int j = 0; j < 4; j++)
                    acc[i][j] = fmaf(a_[i], e_[j], acc[i][j]);
        }
        __syncthreads();
    }

    #pragma unroll
    for (int i = 0; i < 4; i++)
        #pragma unroll
        for (int j = 0; j < 4; j++)
            L[tb * 4 + i][te * 4 + j] = acc[i][j];
    __syncthreads();

    if (tid < 64) {
        int b = b0 + tid;
        float v[E_SZ];
        float mx = -1e30f;
        #pragma unroll
        for (int e = 0; e < E_SZ; e++) {
            float u = gu[(size_t)b * E_SZ + e];
            float g = -logf(-logf(u + 1e-10f) + 1e-10f);
            float t = L[tid][e] + b_att[e] + abias[e] + g;   // TAU = 1.0
            v[e] = t;
            mx = fmaxf(mx, t);
        }
        float s = 0.f;
        #pragma unroll
        for (int e = 0; e < E_SZ; e++) { v[e] = expf(v[e] - mx); s += v[e]; }
        float inv = 1.f / s;
        #pragma unroll
        for (int e = 0; e < E_SZ; e++) {
            float w = v[e] * inv;
            Wg[tid][e] = w;
            g_weights[(size_t)b * E_SZ + e] = w;
        }
    }
    __syncthreads();

    // Seed d_out with sum_e w[b,e]*b_strat[e,a].
    for (int idx = tid; idx < 64 * A_SZ; idx += 128) {
        int r = idx >> 7, a = idx & 127;
        float s = 0.f;
        #pragma unroll
        for (int e = 0; e < E_SZ; e++)
            s = fmaf(Wg[r][e], b_strat[e * A_SZ + a], s);
        out[(size_t)(b0 + r) * A_SZ + a] = s;
    }
}

// =====================================================================
// Kernel 2: out[b,a] += sum_e sum_d (w[b,e]*x[b,d]) * W_strat[e,a,d]
// BM=128, BN=64, BK=16, 128 threads, 8x8 thread tile, f32x2 FMAs,
// register-staged double-buffered smem, one barrier per K-tile.
// Grid: (64, 2) = 128 CTAs.
// =====================================================================
#define BM 128
#define BN 64
#define BK 16

__global__ __launch_bounds__(128) void main_kernel(
    const float* __restrict__ x, const float* __restrict__ W_strat,
    float* __restrict__ out)
{
    __shared__ float xs[2][BK][BM];
    __shared__ float ws[2][BK][BN];

    const int tid = threadIdx.x;
    const int tx = tid & 7;     // 8 col-groups
    const int ty = tid >> 3;    // 16 row-groups
    const int b0 = blockIdx.x * BM;
    const int a0 = blockIdx.y * BN;

    unsigned long long acc[8][4];
    #pragma unroll
    for (int i = 0; i < 8; i++)
        #pragma unroll
        for (int p = 0; p < 4; p++) acc[i][p] = 0ull;

    const int NT = E_SZ * (D_SZ / BK);   // 2048 K-tiles

    float4 xr[4];
    float  wr[4];
    float4 wvr[2];

    // ---- tile loader: global -> registers (x scaled by gating weight at STS) ----
    auto ldg_tile = [&](int kt) {
        const int e  = kt >> 6;            // 64 d-tiles per expert
        const int d0 = (kt & 63) * BK;
        #pragma unroll
        for (int i = 0; i < 4; i++) {
            int f = tid + i * 128;
            int row = f >> 2, c4 = f & 3;
            xr[i] = *(const float4*)&x[(size_t)(b0 + row) * D_SZ + d0 + c4 * 4];
            wr[i] = g_weights[(size_t)(b0 + row) * E_SZ + e];
        }
        #pragma unroll
        for (int i = 0; i < 2; i++) {
            int f = tid + i * 128;
            int row = f >> 2, c4 = f & 3;
            wvr[i] = *(const float4*)&W_strat[((size_t)e * A_SZ + a0 + row) * D_SZ + d0 + c4 * 4];
        }
    };
    auto sts_tile = [&](int buf) {
        #pragma unroll
        for (int i = 0; i < 4; i++) {
            int f = tid + i * 128;
            int row = f >> 2, c4 = f & 3;
            float w = wr[i];
            xs[buf][c4 * 4 + 0][row] = xr[i].x * w;
            xs[buf][c4 * 4 + 1][row] = xr[i].y * w;
            xs[buf][c4 * 4 + 2][row] = xr[i].z * w;
            xs[buf][c4 * 4 + 3][row] = xr[i].w * w;
        }
        #pragma unroll
        for (int i = 0; i < 2; i++) {
            int f = tid + i * 128;
            int row = f >> 2, c4 = f & 3;
            ws[buf][c4 * 4 + 0][row] = wvr[i].x;
            ws[buf][c4 * 4 + 1][row] = wvr[i].y;
            ws[buf][c4 * 4 + 2][row] = wvr[i].z;
            ws[buf][c4 * 4 + 3][row] = wvr[i].w;
        }
    };

    ldg_tile(0);
    sts_tile(0);
    int buf = 0;

    for (int kt = 0; kt < NT; kt++) {
        if (kt + 1 < NT) ldg_tile(kt + 1);
        __syncthreads();                      // STS(buf) visible; prev compute done
        #pragma unroll
        for (int kk = 0; kk < BK; kk++) {
            float4 A0 = *(const float4*)&xs[buf][kk][ty * 4];
            float4 A1 = *(const float4*)&xs[buf][kk][64 + ty * 4];
            float4 B0 = *(const float4*)&ws[buf][kk][tx * 4];
            float4 B1 = *(const float4*)&ws[buf][kk][32 + tx * 4];
            unsigned long long bp[4] = {
                pack2(B0.x, B0.y), pack2(B0.z, B0.w),
                pack2(B1.x, B1.y), pack2(B1.z, B1.w)
            };
            float av[8] = {A0.x, A0.y, A0.z, A0.w, A1.x, A1.y, A1.z, A1.w};
            #pragma unroll
            for (int i = 0; i < 8; i++) {
                unsigned long long ai = pack2(av[i], av[i]);
                #pragma unroll
                for (int p = 0; p < 4; p++) ffma2(acc[i][p], ai, bp[p]);
            }
        }
        if (kt + 1 < NT) sts_tile(buf ^ 1);   // safe: buf^1 last read before top sync
        buf ^= 1;
    }

    // ---- epilogue: accumulate onto bias term already in d_out ----
    #pragma unroll
    for (int g = 0; g < 2; g++) {
        #pragma unroll
        for (int ii = 0; ii < 4; ii++) {
            int i = g * 4 + ii;
            size_t rowoff = (size_t)(b0 + g * 64 + ty * 4 + ii) * A_SZ + a0;
            float lo, hi;
            float4 o0 = *(float4*)&out[rowoff + tx * 4];
            unpack2(acc[i][0], lo, hi); o0.x += lo; o0.y += hi;
            unpack2(acc[i][1], lo, hi); o0.z += lo; o0.w += hi;
            *(float4*)&out[rowoff + tx * 4] = o0;
            float4 o1 = *(float4*)&out[rowoff + 32 + tx * 4];
            unpack2(acc[i][2], lo, hi); o1.x += lo; o1.y += hi;
            unpack2(acc[i][3], lo, hi); o1.z += lo; o1.w += hi;
            *(float4*)&out[rowoff + 32 + tx * 4] = o1;
        }
    }
}

// =====================================================================
// Launch: gating first (writes g_weights + bias term into d_out),
// then the fused weighted GEMM accumulating into d_out.
// =====================================================================
extern "C" void kernel_launch(void* const* d_in, const int* in_sizes, int n_in,
                              void* d_out, int out_size) {
    const float* x        = (const float*)d_in[0];
    const float* W_att    = (const float*)d_in[1];
    const float* b_att    = (const float*)d_in[2];
    const float* abias    = (const float*)d_in[3];
    const float* W_strat  = (const float*)d_in[4];
    const float* b_strat  = (const float*)d_in[5];
    const float* gu       = (const float*)d_in[6];
    float* out = (float*)d_out;

    gating_kernel<<<B_SZ / 64, 128>>>(x, W_att, b_att, abias, b_strat, gu, out);
    main_kernel<<<dim3(B_SZ / BM, A_SZ / BN), 128>>>(x, W_strat, out);
}

// round 3
// speedup vs baseline: 3.5927x; 3.5927x over previous
#include <cuda_runtime.h>
#include <cstdint>

#define B_SZ 8192
#define D_SZ 1024
#define E_SZ 32
#define A_SZ 128

// gating weights (kernel1 -> kernel3); W_strat pre-converted to tf32 (kernel2 -> kernel3)
__device__ float    g_weights[B_SZ * E_SZ];
__device__ uint32_t g_wtf32[(size_t)E_SZ * A_SZ * D_SZ];   // 16 MB

// ===================== helpers =====================
__device__ __forceinline__ uint32_t smem_u32(const void* p) {
    uint32_t a;
    asm("{ .reg .u64 t; cvta.to.shared.u64 t, %1; cvt.u32.u64 %0, t; }" : "=r"(a) : "l"(p));
    return a;
}
__device__ __forceinline__ uint32_t f2tf32(float f) {
    uint32_t u;
    asm("cvt.rna.tf32.f32 %0, %1;" : "=r"(u) : "f"(f));
    return u;
}
__device__ __forceinline__ void cp16(uint32_t dst, const void* src) {
    asm volatile("cp.async.cg.shared.global [%0], [%1], 16;" :: "r"(dst), "l"(src));
}
#define CP_COMMIT() asm volatile("cp.async.commit_group;" ::: "memory")
#define CP_WAIT2()  asm volatile("cp.async.wait_group 2;" ::: "memory")

// D += A(16x8 tf32, row) * B(8x8 tf32, col)
__device__ __forceinline__ void mma8(float* c, const uint32_t* a, uint32_t b0, uint32_t b1) {
    asm volatile(
        "mma.sync.aligned.m16n8k8.row.col.f32.tf32.tf32.f32 "
        "{%0,%1,%2,%3}, {%4,%5,%6,%7}, {%8,%9}, {%0,%1,%2,%3};"
        : "+f"(c[0]), "+f"(c[1]), "+f"(c[2]), "+f"(c[3])
        : "r"(a[0]), "r"(a[1]), "r"(a[2]), "r"(a[3]), "r"(b0), "r"(b1));
}

// =====================================================================
// Kernel 1: gating (R1, known-correct). Seeds out with bias term.
// =====================================================================
__global__ __launch_bounds__(128) void gating_kernel(
    const float* __restrict__ x, const float* __restrict__ W_att,
    const float* __restrict__ b_att, const float* __restrict__ abias,
    const float* __restrict__ b_strat, const float* __restrict__ gu,
    float* __restrict__ out)
{
    __shared__ float xs[32][64];
    __shared__ float was[32][32];
    __shared__ float L[64][33];
    __shared__ float Wg[64][33];

    const int tid = threadIdx.x;
    const int b0 = blockIdx.x * 64;
    const int tb = tid & 15;
    const int te = tid >> 4;

    float acc[4][4] = {};

    for (int d0 = 0; d0 < D_SZ; d0 += 32) {
        #pragma unroll
        for (int i = 0; i < 4; i++) {
            int f = tid + i * 128;
            int row = f >> 3, c4 = f & 7;
            float4 v = *(const float4*)&x[(size_t)(b0 + row) * D_SZ + d0 + c4 * 4];
            xs[c4 * 4 + 0][row] = v.x; xs[c4 * 4 + 1][row] = v.y;
            xs[c4 * 4 + 2][row] = v.z; xs[c4 * 4 + 3][row] = v.w;
        }
        #pragma unroll
        for (int i = 0; i < 2; i++) {
            int f = tid + i * 128;
            int row = f >> 3, c4 = f & 7;
            float4 v = *(const float4*)&W_att[(size_t)row * D_SZ + d0 + c4 * 4];
            was[c4 * 4 + 0][row] = v.x; was[c4 * 4 + 1][row] = v.y;
            was[c4 * 4 + 2][row] = v.z; was[c4 * 4 + 3][row] = v.w;
        }
        __syncthreads();
        #pragma unroll 8
        for (int kk = 0; kk < 32; kk++) {
            float4 av = *(const float4*)&xs[kk][tb * 4];
            float4 ev = *(const float4*)&was[kk][te * 4];
            float a_[4] = {av.x, av.y, av.z, av.w};
            float e_[4] = {ev.x, ev.y, ev.z, ev.w};
            #pragma unroll
            for (int i = 0; i < 4; i++)
                #pragma unroll
                for (int j = 0; j < 4; j++)
                    acc[i][j] = fmaf(a_[i], e_[j], acc[i][j]);
        }
        __syncthreads();
    }

    #pragma unroll
    for (int i = 0; i < 4; i++)
        #pragma unroll
        for (int j = 0; j < 4; j++)
            L[tb * 4 + i][te * 4 + j] = acc[i][j];
    __syncthreads();

    if (tid < 64) {
        int b = b0 + tid;
        float v[E_SZ];
        float mx = -1e30f;
        #pragma unroll
        for (int e = 0; e < E_SZ; e++) {
            float u = gu[(size_t)b * E_SZ + e];
            float g = -logf(-logf(u + 1e-10f) + 1e-10f);
            float t = L[tid][e] + b_att[e] + abias[e] + g;   // TAU = 1.0
            v[e] = t;
            mx = fmaxf(mx, t);
        }
        float s = 0.f;
        #pragma unroll
        for (int e = 0; e < E_SZ; e++) { v[e] = expf(v[e] - mx); s += v[e]; }
        float inv = 1.f / s;
        #pragma unroll
        for (int e = 0; e < E_SZ; e++) {
            float w = v[e] * inv;
            Wg[tid][e] = w;
            g_weights[(size_t)b * E_SZ + e] = w;
        }
    }
    __syncthreads();

    for (int idx = tid; idx < 64 * A_SZ; idx += 128) {
        int r = idx >> 7, a = idx & 127;
        float s = 0.f;
        #pragma unroll
        for (int e = 0; e < E_SZ; e++)
            s = fmaf(Wg[r][e], b_strat[e * A_SZ + a], s);
        out[(size_t)(b0 + r) * A_SZ + a] = s;
    }
}

// =====================================================================
// Kernel 2: W_strat -> tf32 (one-time per launch, 16 MB)
// =====================================================================
__global__ __launch_bounds__(256) void convert_w_kernel(const float* __restrict__ W)
{
    size_t i = (size_t)blockIdx.x * 256 + threadIdx.x;   // float4 index
    float4 v = ((const float4*)W)[i];
    uint4 o;
    o.x = f2tf32(v.x); o.y = f2tf32(v.y);
    o.z = f2tf32(v.z); o.w = f2tf32(v.w);
    ((uint4*)g_wtf32)[i] = o;
}

// =====================================================================
// Kernel 3: fused weighted GEMM on mma.sync tf32.
// CTA tile 128(M) x 64(N), 8 warps (4Mx2N), warp tile 32x32, BK=32.
// A-fragments: raw x loaded once per d-chunk, scaled by w[b,e] per expert
// in registers (+ cvt.rna.tf32). B: pre-converted tf32 W via cp.async.
// W: 4-stage ring, prefetch distance 2; x: 2-stage; 1 barrier/iter.
// =====================================================================
#define XS_OFF   16384                      // after w_s (32*128*4)
#define XBUF_B   18432                      // 128 rows * 36 * 4
#define WS_OFF   (XS_OFF + 2 * XBUF_B)      // 53248
#define WBUF_B   9216                       // 64 rows * 36 * 4
#define SMEM_TOT (WS_OFF + 4 * WBUF_B)      // 90112

__global__ __launch_bounds__(256, 1) void main_kernel(
    const float* __restrict__ x, float* __restrict__ out)
{
    extern __shared__ char smem[];
    float* w_s = (float*)smem;                       // [e][128]
    const uint32_t sb = smem_u32(smem);
    const int tid = threadIdx.x;
    const int lane = tid & 31, wid = tid >> 5;
    const int warpM = wid >> 1, warpN = wid & 1;
    const int g = lane >> 2, qc = lane & 3;
    const int brow0 = blockIdx.x * 128;
    const int acol0 = blockIdx.y * 64;

    // gating weights for this CTA's 128 rows, all experts
    for (int i = tid; i < E_SZ * 128; i += 256) {
        int e = i >> 7, r = i & 127;
        w_s[i] = g_weights[(size_t)(brow0 + r) * E_SZ + e];
    }

    auto cp_x = [&](int dc) {
        uint32_t base = sb + XS_OFF + (dc & 1) * XBUF_B;
        const float* src = x + (size_t)brow0 * D_SZ + dc * 32;
        #pragma unroll
        for (int j = 0; j < 4; j++) {
            int f = tid + j * 256;
            int row = f >> 3, c4 = f & 7;
            cp16(base + row * 144 + c4 * 16, src + (size_t)row * D_SZ + c4 * 4);
        }
    };
    auto cp_w = [&](int t) {
        int dc = t >> 5, e = t & 31;
        uint32_t base = sb + WS_OFF + (t & 3) * WBUF_B;
        const uint32_t* src = g_wtf32 + ((size_t)e * A_SZ + acol0) * D_SZ + dc * 32;
        #pragma unroll
        for (int j = 0; j < 2; j++) {
            int f = tid + j * 256;
            int a = f >> 3, c4 = f & 7;
            cp16(base + a * 144 + c4 * 16, src + (size_t)a * D_SZ + c4 * 4);
        }
    };

    cp_x(0); cp_w(0); CP_COMMIT();
    cp_w(1); CP_COMMIT();
    __syncthreads();   // w_s visible

    float acc[2][4][4] = {};
    float rawA[4][2][4];

    const float* xsf = (const float*)(smem + XS_OFF);
    const uint32_t* wsu = (const uint32_t*)(smem + WS_OFF);

    const int NT = (D_SZ / 32) * E_SZ;   // 1024
    for (int t = 0; t < NT; t++) {
        int dc = t >> 5, e = t & 31;
        if (t + 2 < NT) cp_w(t + 2);
        if (e == 28 && dc < 31) cp_x(dc + 1);
        CP_COMMIT();
        CP_WAIT2();
        __syncthreads();

        if (e == 0) {
            const float* xb = xsf + (dc & 1) * (XBUF_B / 4);
            #pragma unroll
            for (int ks = 0; ks < 4; ks++)
                #pragma unroll
                for (int mt = 0; mt < 2; mt++) {
                    int rb = warpM * 32 + mt * 16 + g;
                    rawA[ks][mt][0] = xb[rb * 36 + ks * 8 + qc];
                    rawA[ks][mt][1] = xb[(rb + 8) * 36 + ks * 8 + qc];
                    rawA[ks][mt][2] = xb[rb * 36 + ks * 8 + qc + 4];
                    rawA[ks][mt][3] = xb[(rb + 8) * 36 + ks * 8 + qc + 4];
                }
        }

        const float* we = w_s + e * 128 + warpM * 32 + g;
        float w0 = we[0], w1 = we[8], w2 = we[16], w3 = we[24];
        const uint32_t* wb = wsu + (t & 3) * (WBUF_B / 4) + (warpN * 32 + g) * 36 + qc;

        #pragma unroll
        for (int ks = 0; ks < 4; ks++) {
            uint32_t sa0[4], sa1[4];
            sa0[0] = f2tf32(rawA[ks][0][0] * w0);
            sa0[1] = f2tf32(rawA[ks][0][1] * w1);
            sa0[2] = f2tf32(rawA[ks][0][2] * w0);
            sa0[3] = f2tf32(rawA[ks][0][3] * w1);
            sa1[0] = f2tf32(rawA[ks][1][0] * w2);
            sa1[1] = f2tf32(rawA[ks][1][1] * w3);
            sa1[2] = f2tf32(rawA[ks][1][2] * w2);
            sa1[3] = f2tf32(rawA[ks][1][3] * w3);
            #pragma unroll
            for (int nt = 0; nt < 4; nt++) {
                uint32_t b0 = wb[nt * 8 * 36 + ks * 8];
                uint32_t b1 = wb[nt * 8 * 36 + ks * 8 + 4];
                mma8(acc[0][nt], sa0, b0, b1);
                mma8(acc[1][nt], sa1, b0, b1);
            }
        }
    }

    // epilogue: accumulate onto bias term already in out
    #pragma unroll
    for (int mt = 0; mt < 2; mt++)
        #pragma unroll
        for (int nt = 0; nt < 4; nt++) {
            int r = brow0 + warpM * 32 + mt * 16 + g;
            int cc = acol0 + warpN * 32 + nt * 8 + qc * 2;
            float2* p0 = (float2*)&out[(size_t)r * A_SZ + cc];
            float2 v0 = *p0;
            v0.x += acc[mt][nt][0]; v0.y += acc[mt][nt][1];
            *p0 = v0;
            float2* p1 = (float2*)&out[(size_t)(r + 8) * A_SZ + cc];
            float2 v1 = *p1;
            v1.x += acc[mt][nt][2]; v1.y += acc[mt][nt][3];
            *p1 = v1;
        }
}

// =====================================================================
extern "C" void kernel_launch(void* const* d_in, const int* in_sizes, int n_in,
                              void* d_out, int out_size) {
    const float* x       = (const float*)d_in[0];
    const float* W_att   = (const float*)d_in[1];
    const float* b_att   = (const float*)d_in[2];
    const float* abias   = (const float*)d_in[3];
    const float* W_strat = (const float*)d_in[4];
    const float* b_strat = (const float*)d_in[5];
    const float* gu      = (const float*)d_in[6];
    float* out = (float*)d_out;

    cudaFuncSetAttribute(main_kernel, cudaFuncAttributeMaxDynamicSharedMemorySize,
                         SMEM_TOT);

    convert_w_kernel<<<((size_t)E_SZ * A_SZ * D_SZ / 4) / 256, 256>>>(W_strat);
    gating_kernel<<<B_SZ / 64, 128>>>(x, W_att, b_att, abias, b_strat, gu, out);
    main_kernel<<<dim3(B_SZ / 128, 2), 256, SMEM_TOT>>>(x, out);
}